// round 1
// baseline (speedup 1.0000x reference)
#include <cuda_runtime.h>

// Problem constants (fixed by the dataset)
#define BATCH 32
#define HW    196      // 14*14 spatial positions
#define C     512      // input channels
#define D     8192     // sketch / output dimension
#define KT    14       // K-chunk for shared tiles (196 = 14*14)

// Fused kernel:
//   grid (4, 4, 32): blockIdx.x = c1 chunk (128 rows), blockIdx.y = c2 chunk
//   (128 cols), blockIdx.z = batch. 256 threads, 8x8 accumulators/thread.
// Computes the 128x128 tile of M[b] = X1[b]^T X2[b] (K = 196), with the
// +/-1 signs s1/s2 folded into the shared-memory tiles at load time, then
// scatters each product into a block-private smem copy of out[b,:] at
// bucket (h1[c1]+h2[c2]) & 8191, and finally atomically flushes to gmem.
__global__ __launch_bounds__(256, 2)
void cbp_fused(const float* __restrict__ x1, const float* __restrict__ x2,
               const float* __restrict__ s1, const float* __restrict__ s2,
               const int*   __restrict__ h1, const int*   __restrict__ h2,
               float* __restrict__ out)
{
    __shared__ float X1s[KT][128];
    __shared__ float X2s[KT][128];
    __shared__ float outacc[D];          // 32 KB private output accumulator

    const int tid = threadIdx.x;
    const int tx  = tid & 15;            // c2 direction
    const int ty  = tid >> 4;            // c1 direction
    const int b   = blockIdx.z;
    const int c1_base = blockIdx.x * 128;
    const int c2_base = blockIdx.y * 128;

    // zero private accumulator
    #pragma unroll
    for (int i = tid; i < D; i += 256) outacc[i] = 0.0f;

    const float* X1 = x1 + (size_t)b * HW * C;
    const float* X2 = x2 + (size_t)b * HW * C;

    // Tile-load mapping: idx = tid + n*256, col = idx & 127 is constant per
    // thread (256 % 128 == 0), so the sign multiplier is loaded once.
    const int   lc  = tid & 127;
    const float s1l = __ldg(&s1[c1_base + lc]);
    const float s2l = __ldg(&s2[c2_base + lc]);

    float acc[8][8];
    #pragma unroll
    for (int i = 0; i < 8; i++)
        #pragma unroll
        for (int j = 0; j < 8; j++) acc[i][j] = 0.0f;

    for (int k0 = 0; k0 < HW; k0 += KT) {
        __syncthreads();   // protect tiles from previous iteration's readers
        #pragma unroll
        for (int n = 0; n < (KT * 128) / 256; ++n) {   // 7 loads per tensor
            int idx = tid + n * 256;
            int kk  = idx >> 7;
            X1s[kk][lc] = X1[(k0 + kk) * C + c1_base + lc] * s1l;
            X2s[kk][lc] = X2[(k0 + kk) * C + c2_base + lc] * s2l;
        }
        __syncthreads();

        #pragma unroll
        for (int kk = 0; kk < KT; ++kk) {
            // split-N fragment layout: lanes tx=0..7 cover all 32 banks once
            float4 a0 = *(const float4*)&X1s[kk][ty * 4];
            float4 a1 = *(const float4*)&X1s[kk][64 + ty * 4];
            float4 b0 = *(const float4*)&X2s[kk][tx * 4];
            float4 b1 = *(const float4*)&X2s[kk][64 + tx * 4];
            float av[8] = {a0.x, a0.y, a0.z, a0.w, a1.x, a1.y, a1.z, a1.w};
            float bv[8] = {b0.x, b0.y, b0.z, b0.w, b1.x, b1.y, b1.z, b1.w};
            #pragma unroll
            for (int i = 0; i < 8; i++)
                #pragma unroll
                for (int j = 0; j < 8; j++)
                    acc[i][j] += av[i] * bv[j];
        }
    }

    // ---- scatter into the block-private accumulator ----
    int h1v[8], h2v[8];
    #pragma unroll
    for (int i = 0; i < 8; i++) {
        int c1 = c1_base + ((i < 4) ? (ty * 4 + i) : (64 + ty * 4 + i - 4));
        h1v[i] = __ldg(&h1[c1]);
    }
    #pragma unroll
    for (int j = 0; j < 8; j++) {
        int c2 = c2_base + ((j < 4) ? (tx * 4 + j) : (64 + tx * 4 + j - 4));
        h2v[j] = __ldg(&h2[c2]);
    }
    #pragma unroll
    for (int i = 0; i < 8; i++) {
        #pragma unroll
        for (int j = 0; j < 8; j++) {
            int d = (h1v[i] + h2v[j]) & (D - 1);
            atomicAdd(&outacc[d], acc[i][j]);
        }
    }

    __syncthreads();
    // ---- flush private accumulator to global output ----
    float* outb = out + (size_t)b * D;
    #pragma unroll
    for (int i = tid; i < D; i += 256) {
        float v = outacc[i];
        if (v != 0.0f) atomicAdd(&outb[i], v);
    }
}

__global__ void zero_out_kernel(float* __restrict__ out, int n)
{
    int i = blockIdx.x * blockDim.x + threadIdx.x;
    if (i < n) out[i] = 0.0f;
}

extern "C" void kernel_launch(void* const* d_in, const int* in_sizes, int n_in,
                              void* d_out, int out_size)
{
    const float* x1 = (const float*)d_in[0];   // bottom1 [32,14,14,512]
    const float* x2 = (const float*)d_in[1];   // bottom2 [32,14,14,512]
    const float* s1 = (const float*)d_in[2];   // rand_s_1 [512]
    const float* s2 = (const float*)d_in[3];   // rand_s_2 [512]
    const int*   h1 = (const int*)d_in[4];     // rand_h_1 [512]
    const int*   h2 = (const int*)d_in[5];     // rand_h_2 [512]
    float* out = (float*)d_out;                // [32, 8192] float32

    const int n = BATCH * D;
    zero_out_kernel<<<(n + 255) / 256, 256>>>(out, n);

    dim3 grid(4, 4, BATCH);   // 512 blocks
    cbp_fused<<<grid, 256>>>(x1, x2, s1, s2, h1, h2, out);
}